// round 1
// baseline (speedup 1.0000x reference)
#include <cuda_runtime.h>

// Problem constants (fixed by setup_inputs)
#define S_LEN   1024
#define D_DIM   32
#define P_STEPS 128
#define L_CHUNK 256                 // s-chunk per warp
#define NCHUNK  (S_LEN / L_CHUNK)   // 4
#define WARPS_PER_BLOCK 8

// out[b,s,d] = sum_{p=0}^{P-1} alpha*beta^p * x[b, s-1-p, d]   (zero for s-1-p < 0)
//            + pos_fwd[d]
//            + pos_bwd[ ((s>>5) - d) & 31 ]
//
// Computed via sliding recurrence:
//   y[s+1] = beta*y[s] + alpha*x[s] - (alpha*beta^P)*x[s-P]
// One warp handles one (b, chunk) row; lane == d. Chunks > 0 warm up y with a
// direct 128-tap sum over the preceding window.
__global__ __launch_bounds__(WARPS_PER_BLOCK * 32)
void attn_pred_kernel(const float* __restrict__ x,
                      const float* __restrict__ alpha_p,
                      const float* __restrict__ beta_p,
                      const float* __restrict__ pos_fwd,
                      const float* __restrict__ pos_bwd,
                      float* __restrict__ out,
                      int n_rows)
{
    const int warp_id = threadIdx.x >> 5;
    const int lane    = threadIdx.x & 31;
    const int row     = blockIdx.x * WARPS_PER_BLOCK + warp_id;
    if (row >= n_rows) return;

    const int b     = row >> 2;      // row / NCHUNK
    const int chunk = row & (NCHUNK - 1);
    const int s0    = chunk * L_CHUNK;

    const float alpha = alpha_p[0];
    const float beta  = beta_p[0];

    const float pf  = pos_fwd[lane];   // pos_fwd_param[0, lane]
    const float pbw = pos_bwd[lane];   // pos_bwd_param[0, lane]

    const float* xrow = x + (b * S_LEN) * D_DIM + lane;

    // ---- warm-up: y = y[s0] = sum_{p=0}^{P-1} alpha*beta^p * x[s0-1-p] ----
    float y = 0.0f;
    float w = alpha;
    if (chunk > 0) {
        const float* pw = xrow + (s0 - 1) * D_DIM;
        #pragma unroll 16
        for (int p = 0; p < P_STEPS; ++p) {
            y = fmaf(w, pw[0], y);
            w *= beta;
            pw -= D_DIM;
        }
    } else {
        #pragma unroll 16
        for (int p = 0; p < P_STEPS; ++p) w *= beta;
    }
    const float c = w;                 // alpha * beta^P

    // ---- main loop over the chunk ----
    const float* pnew = xrow + s0 * D_DIM;
    const float* pold = pnew - P_STEPS * D_DIM;   // guarded load when s < P
    float* pout = out + ((b * S_LEN) + s0) * D_DIM + lane;

    int s = s0;
    #pragma unroll 1
    for (int grp = 0; grp < L_CHUNK / 32; ++grp) {
        // bucket index is constant inside a 32-aligned s-group:
        //   idx = ((s>>5) - d) & 31
        const int idx = ((s >> 5) - lane) & 31;
        const float addv = pf + __shfl_sync(0xffffffffu, pbw, idx);
        #pragma unroll
        for (int i = 0; i < 32; ++i) {
            pout[0] = y + addv;
            const float xn = pnew[0];
            const float xo = (s >= P_STEPS) ? pold[0] : 0.0f;
            y = fmaf(beta, y, fmaf(alpha, xn, -c * xo));
            pnew += D_DIM;
            pold += D_DIM;
            pout += D_DIM;
            ++s;
        }
    }
}

extern "C" void kernel_launch(void* const* d_in, const int* in_sizes, int n_in,
                              void* d_out, int out_size)
{
    const float* x     = (const float*)d_in[0];
    const float* alpha = (const float*)d_in[1];
    const float* beta  = (const float*)d_in[2];
    const float* pf    = (const float*)d_in[3];
    const float* pb    = (const float*)d_in[4];
    // d_in[5] (past_steps) is fixed at 128; hardcoded as P_STEPS.

    const int B = in_sizes[0] / (S_LEN * D_DIM);   // 1024
    const int n_rows = B * NCHUNK;                 // 4096
    const int n_blocks = (n_rows + WARPS_PER_BLOCK - 1) / WARPS_PER_BLOCK; // 512

    attn_pred_kernel<<<n_blocks, WARPS_PER_BLOCK * 32>>>(
        x, alpha, beta, pf, pb, (float*)d_out, n_rows);
}

// round 2
// speedup vs baseline: 1.1461x; 1.1461x over previous
#include <cuda_runtime.h>

// Problem constants (fixed by setup_inputs)
#define S_LEN   1024
#define D_DIM   32
#define P_STEPS 128
#define L_CHUNK 128                 // s-chunk per warp
#define NCHUNK  (S_LEN / L_CHUNK)   // 8
#define WPB     8                   // warps per block; block = all 8 chunks of one b

// out[b,s,d] = sum_{p=0}^{P-1} alpha*beta^p * x[b, s-1-p, d]
//            + pos_fwd[d] + pos_bwd[ ((s>>5) - d) & 31 ]
//
// Sliding recurrence: y[s+1] = beta*y[s] + alpha*x[s] - (alpha*beta^P)*x[s-P]
// One warp per (b, chunk); lane == d. Chunks > 0 warm up with a direct 128-tap
// weighted sum (4-way split dependence chains, weight stepped by beta^4).
__global__ __launch_bounds__(WPB * 32)
void attn_pred_kernel(const float* __restrict__ x,
                      const float* __restrict__ alpha_p,
                      const float* __restrict__ beta_p,
                      const float* __restrict__ pos_fwd,
                      const float* __restrict__ pos_bwd,
                      float* __restrict__ out)
{
    const int warp_id = threadIdx.x >> 5;
    const int lane    = threadIdx.x & 31;
    const int row     = blockIdx.x * WPB + warp_id;

    const int b     = row >> 3;              // row / NCHUNK
    const int chunk = row & (NCHUNK - 1);
    const int s0    = chunk * L_CHUNK;

    const float alpha = alpha_p[0];
    const float beta  = beta_p[0];
    const float b2    = beta * beta;
    const float b4    = b2 * b2;

    const float pf  = pos_fwd[lane];
    const float pbw = pos_bwd[lane];

    const float* xrow = x + (size_t)b * S_LEN * D_DIM + lane;
    const float* pnew = xrow + s0 * D_DIM;
    float*       pout = out + ((size_t)b * S_LEN + s0) * D_DIM + lane;

    float y = 0.0f;

    if (chunk == 0) {
        // ---- chunk 0: no history, no old-tap subtraction anywhere ----
        #pragma unroll 1
        for (int grp = 0; grp < L_CHUNK / 32; ++grp) {
            const int idx = ((s0 >> 5) + grp - lane) & 31;
            const float addv = pf + __shfl_sync(0xffffffffu, pbw, idx);
            #pragma unroll
            for (int i = 0; i < 32; ++i) {
                __stcs(pout, y + addv);
                y = fmaf(beta, y, alpha * pnew[0]);
                pnew += D_DIM;
                pout += D_DIM;
            }
        }
    } else {
        // ---- warm-up: y[s0] = sum_{p=0}^{127} alpha*beta^p * x[s0-1-p] ----
        const float* pw = xrow + (s0 - 1) * D_DIM;
        float y0 = 0.f, y1 = 0.f, y2 = 0.f, y3 = 0.f;
        float wk = alpha;
        #pragma unroll 8
        for (int p = 0; p < P_STEPS; p += 4) {
            y0 = fmaf(wk, pw[0],          y0);
            y1 = fmaf(wk, pw[-1 * D_DIM], y1);
            y2 = fmaf(wk, pw[-2 * D_DIM], y2);
            y3 = fmaf(wk, pw[-3 * D_DIM], y3);
            wk *= b4;
            pw -= 4 * D_DIM;
        }
        y = fmaf(b2, fmaf(beta, y3, y2), fmaf(beta, y1, y0));
        const float c = wk;                       // alpha * beta^128

        // ---- main loop: all steps have s >= P, old tap always valid ----
        const float* pold = pnew - P_STEPS * D_DIM;
        #pragma unroll 1
        for (int grp = 0; grp < L_CHUNK / 32; ++grp) {
            const int idx = ((s0 >> 5) + grp - lane) & 31;
            const float addv = pf + __shfl_sync(0xffffffffu, pbw, idx);
            #pragma unroll
            for (int i = 0; i < 32; ++i) {
                __stcs(pout, y + addv);
                const float xn = pnew[0];
                const float xo = pold[0];
                y = fmaf(beta, y, fmaf(alpha, xn, -c * xo));
                pnew += D_DIM;
                pold += D_DIM;
                pout += D_DIM;
            }
        }
    }
}

extern "C" void kernel_launch(void* const* d_in, const int* in_sizes, int n_in,
                              void* d_out, int out_size)
{
    const float* x     = (const float*)d_in[0];
    const float* alpha = (const float*)d_in[1];
    const float* beta  = (const float*)d_in[2];
    const float* pf    = (const float*)d_in[3];
    const float* pb    = (const float*)d_in[4];
    // d_in[5] (past_steps) fixed at 128 -> P_STEPS.

    const int B = in_sizes[0] / (S_LEN * D_DIM);   // 1024
    const int n_blocks = B * NCHUNK / WPB;         // 1024 (one b per block)

    attn_pred_kernel<<<n_blocks, WPB * 32>>>(x, alpha, beta, pf, pb, (float*)d_out);
}

// round 3
// speedup vs baseline: 1.3695x; 1.1950x over previous
#include <cuda_runtime.h>

// Problem constants (fixed by setup_inputs)
#define S_LEN   1024
#define D_DIM   32
#define P_STEPS 128
#define L_CHUNK 128
#define NCHUNK  8                   // S_LEN / L_CHUNK
#define RPW     4                   // rows per warp (8 lanes x float4 each)
#define WPB     2                   // warps per block (64 threads)

// out[b,s,d] = sum_{p=0}^{127} alpha*beta^p * x[b, s-1-p, d]
//            + pos_fwd[d] + pos_bwd[ ((s>>5) - d) & 31 ]
// Sliding recurrence: y[s+1] = beta*y[s] + alpha*x[s] - (alpha*beta^128)*x[s-128]
//
// Thread layout: 8 threads per (b,chunk) row, each owning 4 d-channels (float4).
// A warp covers 4 rows = 4 consecutive b with the SAME chunk (chunk is
// warp-uniform -> clean branch for the chunk-0 specialization).
__global__ __launch_bounds__(WPB * 32, 8)
void attn_pred_kernel(const float* __restrict__ x,
                      const float* __restrict__ alpha_p,
                      const float* __restrict__ beta_p,
                      const float* __restrict__ pos_fwd,
                      const float* __restrict__ pos_bwd,
                      float* __restrict__ out)
{
    const int lane  = threadIdx.x & 31;
    const int wg    = blockIdx.x * WPB + (threadIdx.x >> 5);  // global warp id
    const int rgrp  = lane >> 3;       // which row inside the warp (0..3)
    const int t8    = lane & 7;        // position within the row (0..7)
    const int chunk = wg & (NCHUNK - 1);            // warp-uniform
    const int b     = ((wg >> 3) << 2) + rgrp;      // 4 consecutive b per warp
    const int s0    = chunk * L_CHUNK;
    const int d0    = t8 << 2;         // first d-channel of this thread

    const float alpha = alpha_p[0];
    const float beta  = beta_p[0];
    const float b2 = beta * beta;
    const float b4 = b2 * b2;

    const float4 pf4 = *(const float4*)(pos_fwd + d0);

    const float*  xrow = x + ((size_t)b * S_LEN) * D_DIM + d0;
    const float4* pnew = (const float4*)(xrow + s0 * D_DIM);
    float4*       pout = (float4*)(out + ((size_t)b * S_LEN + s0) * D_DIM + d0);

    if (chunk == 0) {
        // ---- chunk 0: no history ----
        float4 y = make_float4(0.f, 0.f, 0.f, 0.f);
        #pragma unroll 1
        for (int grp = 0; grp < L_CHUNK / 32; ++grp) {
            float4 av;
            av.x = pf4.x + __ldg(pos_bwd + ((grp - d0    ) & 31));
            av.y = pf4.y + __ldg(pos_bwd + ((grp - d0 - 1) & 31));
            av.z = pf4.z + __ldg(pos_bwd + ((grp - d0 - 2) & 31));
            av.w = pf4.w + __ldg(pos_bwd + ((grp - d0 - 3) & 31));
            #pragma unroll
            for (int i = 0; i < 32; ++i) {
                __stcs(pout, make_float4(y.x + av.x, y.y + av.y,
                                         y.z + av.z, y.w + av.w));
                const float4 xn = *pnew;
                y.x = fmaf(beta, y.x, alpha * xn.x);
                y.y = fmaf(beta, y.y, alpha * xn.y);
                y.z = fmaf(beta, y.z, alpha * xn.z);
                y.w = fmaf(beta, y.w, alpha * xn.w);
                pnew += D_DIM / 4;
                pout += D_DIM / 4;
            }
        }
    } else {
        // ---- warm-up: y[s0] = sum_{p=0}^{127} alpha*beta^p * x[s0-1-p] ----
        const float4* pw = (const float4*)(xrow + (s0 - 1) * D_DIM);
        float4 a0 = make_float4(0,0,0,0), a1 = a0, a2v = a0, a3 = a0;
        float wk = alpha;
        #pragma unroll 4
        for (int p = 0; p < P_STEPS; p += 4) {
            const float4 v0 = pw[0];
            const float4 v1 = pw[-1 * (D_DIM / 4)];
            const float4 v2 = pw[-2 * (D_DIM / 4)];
            const float4 v3 = pw[-3 * (D_DIM / 4)];
            a0.x = fmaf(wk, v0.x, a0.x);  a0.y = fmaf(wk, v0.y, a0.y);
            a0.z = fmaf(wk, v0.z, a0.z);  a0.w = fmaf(wk, v0.w, a0.w);
            a1.x = fmaf(wk, v1.x, a1.x);  a1.y = fmaf(wk, v1.y, a1.y);
            a1.z = fmaf(wk, v1.z, a1.z);  a1.w = fmaf(wk, v1.w, a1.w);
            a2v.x = fmaf(wk, v2.x, a2v.x); a2v.y = fmaf(wk, v2.y, a2v.y);
            a2v.z = fmaf(wk, v2.z, a2v.z); a2v.w = fmaf(wk, v2.w, a2v.w);
            a3.x = fmaf(wk, v3.x, a3.x);  a3.y = fmaf(wk, v3.y, a3.y);
            a3.z = fmaf(wk, v3.z, a3.z);  a3.w = fmaf(wk, v3.w, a3.w);
            wk *= b4;
            pw -= 4 * (D_DIM / 4);
        }
        float4 y;
        y.x = fmaf(b2, fmaf(beta, a3.x, a2v.x), fmaf(beta, a1.x, a0.x));
        y.y = fmaf(b2, fmaf(beta, a3.y, a2v.y), fmaf(beta, a1.y, a0.y));
        y.z = fmaf(b2, fmaf(beta, a3.z, a2v.z), fmaf(beta, a1.z, a0.z));
        y.w = fmaf(b2, fmaf(beta, a3.w, a2v.w), fmaf(beta, a1.w, a0.w));
        const float c = wk;                       // alpha * beta^128

        // ---- main loop: old tap always valid ----
        const float4* pold = pnew - P_STEPS * (D_DIM / 4);
        #pragma unroll 1
        for (int grp = 0; grp < L_CHUNK / 32; ++grp) {
            const int gabs = (s0 >> 5) + grp;
            float4 av;
            av.x = pf4.x + __ldg(pos_bwd + ((gabs - d0    ) & 31));
            av.y = pf4.y + __ldg(pos_bwd + ((gabs - d0 - 1) & 31));
            av.z = pf4.z + __ldg(pos_bwd + ((gabs - d0 - 2) & 31));
            av.w = pf4.w + __ldg(pos_bwd + ((gabs - d0 - 3) & 31));
            #pragma unroll
            for (int i = 0; i < 32; ++i) {
                __stcs(pout, make_float4(y.x + av.x, y.y + av.y,
                                         y.z + av.z, y.w + av.w));
                const float4 xn = *pnew;
                const float4 xo = *pold;
                y.x = fmaf(beta, y.x, fmaf(alpha, xn.x, -(c * xo.x)));
                y.y = fmaf(beta, y.y, fmaf(alpha, xn.y, -(c * xo.y)));
                y.z = fmaf(beta, y.z, fmaf(alpha, xn.z, -(c * xo.z)));
                y.w = fmaf(beta, y.w, fmaf(alpha, xn.w, -(c * xo.w)));
                pnew += D_DIM / 4;
                pold += D_DIM / 4;
                pout += D_DIM / 4;
            }
        }
    }
}

extern "C" void kernel_launch(void* const* d_in, const int* in_sizes, int n_in,
                              void* d_out, int out_size)
{
    const float* x     = (const float*)d_in[0];
    const float* alpha = (const float*)d_in[1];
    const float* beta  = (const float*)d_in[2];
    const float* pf    = (const float*)d_in[3];
    const float* pb    = (const float*)d_in[4];
    // d_in[5] (past_steps) fixed at 128 -> P_STEPS.

    const int B = in_sizes[0] / (S_LEN * D_DIM);        // 1024
    const int n_warps  = (B / RPW) * NCHUNK;            // 2048
    const int n_blocks = n_warps / WPB;                 // 1024

    attn_pred_kernel<<<n_blocks, WPB * 32>>>(x, alpha, beta, pf, pb, (float*)d_out);
}